// round 10
// baseline (speedup 1.0000x reference)
#include <cuda_runtime.h>
#include <math.h>
#include <stdint.h>

// Problem constants: B=8, N=4096, C=512, NH=8, HD=64, R=8, H=W=64, M=64, EPS=1e-3

#define NB   8
#define NSEQ 4096
#define CD   512
#define NHH  8

// ---------------- scratch (device globals; no allocation allowed) ----------------
__device__ float g_q[(size_t)NB * NSEQ * CD];      // [B, N, nh*64+hd]
__device__ float g_attn[(size_t)NB * NSEQ * CD];   // [B, N, nh*64+hd]
__device__ float g_fpart[(size_t)8 * 512 * 512];   // conv partials (8 ry) / kv partials (4 splits)
__device__ float g_ln[512 * 512];                  // layernormed fmap [B*64, C]
__device__ float g_kv[512 * 1024];                 // [B*64, 2C]

// ---------------- helpers ----------------
__device__ __forceinline__ uint32_t f2tf32(float v) {
    uint32_t u;
    asm("cvt.rna.tf32.f32 %0, %1;" : "=r"(u) : "f"(v));
    return u;
}

__device__ __forceinline__ void mma_tf32(float* d, const uint32_t* a, const uint32_t* b) {
    asm volatile(
        "mma.sync.aligned.m16n8k8.row.col.f32.tf32.tf32.f32 "
        "{%0,%1,%2,%3}, {%4,%5,%6,%7}, {%8,%9}, {%0,%1,%2,%3};"
        : "+f"(d[0]), "+f"(d[1]), "+f"(d[2]), "+f"(d[3])
        : "r"(a[0]), "r"(a[1]), "r"(a[2]), "r"(a[3]), "r"(b[0]), "r"(b[1]));
}

__device__ __forceinline__ unsigned long long ffma2(unsigned long long a,
                                                    unsigned long long b,
                                                    unsigned long long c) {
    unsigned long long d;
    asm("fma.rn.f32x2 %0, %1, %2, %3;" : "=l"(d) : "l"(a), "l"(b), "l"(c));
    return d;
}

__device__ __forceinline__ unsigned long long pack2(float x) {
    unsigned long long r;
    asm("mov.b64 %0, {%1, %1};" : "=l"(r) : "f"(x));
    return r;
}

// =====================================================================
// R7 tf32 GEMM core: 128x128 CTA tile, BK=32, 8 warps of 64x32.
// Double-buffered dynamic smem (2 x 32KB). Fragment-major layout with
// XOR swizzles:  A field ^= (k8&3)<<2 ;  B field ^= (ni&15)<<1
// a-reg map (m16k8): a0=A[g][c] a1=A[g+8][c] a2=A[g][c+4] a3=A[g+8][c+4]
// b-reg map (k8n8):  b0=B[c][g]  b1=B[c+4][g],   lane=(g<<2)|c
// =====================================================================
#define GEMM_SMEM (2 * 8192 * 4 * 2)   // 64KB

#define GEMM_PREAMBLE()                                                         \
    extern __shared__ uint32_t dynsmem[];                                       \
    const int tid  = threadIdx.x;                                               \
    const int lane = tid & 31, warp = tid >> 5;                                 \
    const int wm = (warp >> 2) << 6;                                            \
    const int wn = (warp & 3) << 5;                                             \
    float acc[4][4][4];                                                         \
    _Pragma("unroll") for (int f = 0; f < 4; f++)                               \
    _Pragma("unroll") for (int g = 0; g < 4; g++)                               \
    _Pragma("unroll") for (int e = 0; e < 4; e++) acc[f][g][e] = 0.f;

__device__ __forceinline__ void sts_tile(uint32_t* As, uint32_t* Bs,
                                         const float4* sa, const float4* sb,
                                         const int* ar, const int* akq,
                                         const int* bkr, const int* bnq) {
#pragma unroll
    for (int l = 0; l < 4; l++) {
        const float* avf = (const float*)&sa[l];
        int r = ar[l], kq = akq[l];
        int rowin16 = r & 15, mi = r >> 4, g = rowin16 & 7;
#pragma unroll
        for (int j = 0; j < 4; j++) {
            int klocal = (kq << 2) + j;
            int k8 = klocal >> 3, koff = klocal & 7;
            int reg = ((koff >> 2) << 1) | (rowin16 >> 3);
            int ln2 = (g << 2) | (koff & 3);
            int fa = ((ln2 << 2) | reg) ^ ((k8 & 3) << 2);
            As[(k8 << 10) + (mi << 7) + fa] = f2tf32(avf[j]);
        }
        const float* bvf = (const float*)&sb[l];
        int kr = bkr[l], nq = bnq[l];
        int k8b = kr >> 3, koffb = kr & 7;
        int regb = koffb >> 2, cb = koffb & 3;
#pragma unroll
        for (int j = 0; j < 4; j++) {
            int nlocal = (nq << 2) + j;
            int ni = nlocal >> 3, gb = nlocal & 7;
            int lnb = (gb << 2) | cb;
            int fb = ((lnb << 1) | regb) ^ ((ni & 15) << 1);
            Bs[(k8b << 10) + (ni << 6) + fb] = f2tf32(bvf[j]);
        }
    }
}

__device__ __forceinline__ void mma_phase(const uint32_t* As, const uint32_t* Bs,
                                          int wm, int wn, int lane,
                                          float acc[4][4][4]) {
#pragma unroll
    for (int k8 = 0; k8 < 4; k8++) {
        uint32_t a[4][4], b[4][2];
#pragma unroll
        for (int f = 0; f < 4; f++) {
            int off = (k8 << 10) + (((wm >> 4) + f) << 7) +
                      (((lane << 2) ^ ((k8 & 3) << 2)));
            *(uint4*)a[f] = *(const uint4*)&As[off];
        }
#pragma unroll
        for (int g = 0; g < 4; g++) {
            int ni = (wn >> 3) + g;
            int off = (k8 << 10) + (ni << 6) +
                      (((lane << 1) ^ ((ni & 15) << 1)));
            *(uint2*)b[g] = *(const uint2*)&Bs[off];
        }
#pragma unroll
        for (int f = 0; f < 4; f++)
#pragma unroll
            for (int g = 0; g < 4; g++) mma_tf32(acc[f][g], a[f], b[g]);
    }
}

// =====================================================================
// Fused conv patch-GEMM + q-projection (independent work, one launch).
//   blocks [0,128):   conv, rows=b*64+m, K=4096 contiguous slice per ry
//   blocks [128,1152): q = x @ Wq_perm, permutation folded into B loads
// =====================================================================
__global__ __launch_bounds__(256, 2)
void fused_convq_kernel(const float* __restrict__ x,
                        const float* __restrict__ Wq,
                        const float* __restrict__ W) {
    GEMM_PREAMBLE();
    const int bx = blockIdx.x;
    const bool isConv = (bx < 128);

    int row0, col0, K, ry = 0;
    if (isConv) {
        ry = bx >> 4;
        int rem = bx & 15;
        row0 = (rem & 3) << 7;
        col0 = (rem >> 2) << 7;
        K = 4096;
    } else {
        int idx = bx - 128;
        row0 = (idx & 255) << 7;
        col0 = (idx >> 8) << 7;
        K = 512;
    }

    int ar[4], akq[4], bkr[4], bnq[4];
    const float* Ap[4];
    const float* Bp[4];
#pragma unroll
    for (int l = 0; l < 4; l++) {
        int idx = tid + (l << 8);
        ar[l]  = idx >> 3;  akq[l] = idx & 7;
        bkr[l] = idx >> 5;  bnq[l] = idx & 31;
        if (isConv) {
            int row = row0 + ar[l];
            int b = row >> 6, m = row & 63;
            int my = m >> 3, mx = m & 7;
            Ap[l] = x + ((size_t)(b << 12) + ((my << 3) + ry) * 64 + (mx << 3)) * 512 + (akq[l] << 2);
            Bp[l] = W + ((size_t)ry * 4096 + bkr[l]) * 512 + col0 + (bnq[l] << 2);
        } else {
            Ap[l] = x + (size_t)(row0 + ar[l]) * 512 + (akq[l] << 2);
            Bp[l] = Wq + (size_t)bkr[l] * 512;   // base row; permuted cols added per load
        }
    }

    float4 sa[4], sb[4];
    uint32_t* buf[2] = {dynsmem, dynsmem + 8192};

    // tile loader (uniform branch per CTA)
    auto load_tile = [&](int k0) {
#pragma unroll
        for (int l = 0; l < 4; l++) {
            sa[l] = *(const float4*)(Ap[l] + k0);
            if (isConv) {
                sb[l] = *(const float4*)(Bp[l] + (size_t)k0 * 512);
            } else {
                const float* bq = Bp[l] + (size_t)k0 * 512;
                int d0 = col0 + (bnq[l] << 2);
                sb[l].x = bq[((d0 & 63) << 3) | (d0 >> 6)];
                int d1 = d0 + 1;
                sb[l].y = bq[((d1 & 63) << 3) | (d1 >> 6)];
                int d2 = d0 + 2;
                sb[l].z = bq[((d2 & 63) << 3) | (d2 >> 6)];
                int d3 = d0 + 3;
                sb[l].w = bq[((d3 & 63) << 3) | (d3 >> 6)];
            }
        }
    };

    load_tile(0);
    sts_tile(buf[0], buf[0] + 4096, sa, sb, ar, akq, bkr, bnq);
    __syncthreads();

    int cur = 0;
    const int nIter = K >> 5;
    for (int it = 1; it < nIter; it++) {
        load_tile(it << 5);
        mma_phase(buf[cur], buf[cur] + 4096, wm, wn, lane, acc);
        sts_tile(buf[cur ^ 1], buf[cur ^ 1] + 4096, sa, sb, ar, akq, bkr, bnq);
        __syncthreads();
        cur ^= 1;
    }
    mma_phase(buf[cur], buf[cur] + 4096, wm, wn, lane, acc);

    const int gq = lane >> 2, cq = lane & 3;
#pragma unroll
    for (int f = 0; f < 4; f++) {
        int mrow = row0 + wm + (f << 4) + gq;
#pragma unroll
        for (int g = 0; g < 4; g++) {
            int col = col0 + wn + (g << 3) + (cq << 1);
            float2 lo = make_float2(acc[f][g][0], acc[f][g][1]);
            float2 hi = make_float2(acc[f][g][2], acc[f][g][3]);
            if (isConv) {
                *(float2*)&g_fpart[((size_t)ry * 512 + mrow) * 512 + col] = lo;
                *(float2*)&g_fpart[((size_t)ry * 512 + mrow + 8) * 512 + col] = hi;
            } else {
                *(float2*)&g_q[(size_t)mrow * 512 + col] = lo;
                *(float2*)&g_q[(size_t)(mrow + 8) * 512 + col] = hi;
            }
        }
    }
}

// =====================================================================
// kv = ln @ Wkv with split-K=4: grid (4, 8, 4), partials into g_fpart
// (g_fpart is free after ln_kernel consumed the conv partials).
// =====================================================================
__global__ __launch_bounds__(256)
void kv_split_kernel(const float* __restrict__ Wkv) {
    GEMM_PREAMBLE();
    const int row0 = blockIdx.x << 7;
    const int col0 = blockIdx.y << 7;
    const int kz   = blockIdx.z;
    const int kbase = kz << 7;

    int ar[4], akq[4], bkr[4], bnq[4];
    const float* Ap[4];
    const float* Bp[4];
#pragma unroll
    for (int l = 0; l < 4; l++) {
        int idx = tid + (l << 8);
        ar[l]  = idx >> 3;  akq[l] = idx & 7;
        Ap[l]  = g_ln + (size_t)(row0 + ar[l]) * 512 + kbase + (akq[l] << 2);
        bkr[l] = idx >> 5;  bnq[l] = idx & 31;
        Bp[l]  = Wkv + (size_t)(kbase + bkr[l]) * 1024 + col0 + (bnq[l] << 2);
    }

    float4 sa[4], sb[4];
    uint32_t* buf[2] = {dynsmem, dynsmem + 8192};

#pragma unroll
    for (int l = 0; l < 4; l++) {
        sa[l] = *(const float4*)(Ap[l]);
        sb[l] = *(const float4*)(Bp[l]);
    }
    sts_tile(buf[0], buf[0] + 4096, sa, sb, ar, akq, bkr, bnq);
    __syncthreads();

    int cur = 0;
    for (int it = 1; it < 4; it++) {
        int k0 = it << 5;
#pragma unroll
        for (int l = 0; l < 4; l++) {
            sa[l] = *(const float4*)(Ap[l] + k0);
            sb[l] = *(const float4*)(Bp[l] + (size_t)k0 * 1024);
        }
        mma_phase(buf[cur], buf[cur] + 4096, wm, wn, lane, acc);
        sts_tile(buf[cur ^ 1], buf[cur ^ 1] + 4096, sa, sb, ar, akq, bkr, bnq);
        __syncthreads();
        cur ^= 1;
    }
    mma_phase(buf[cur], buf[cur] + 4096, wm, wn, lane, acc);

    const int gq = lane >> 2, cq = lane & 3;
#pragma unroll
    for (int f = 0; f < 4; f++) {
        int mrow = row0 + wm + (f << 4) + gq;
#pragma unroll
        for (int g = 0; g < 4; g++) {
            int col = col0 + wn + (g << 3) + (cq << 1);
            *(float2*)&g_fpart[((size_t)kz << 19) + (size_t)mrow * 1024 + col] =
                make_float2(acc[f][g][0], acc[f][g][1]);
            *(float2*)&g_fpart[((size_t)kz << 19) + (size_t)(mrow + 8) * 1024 + col] =
                make_float2(acc[f][g][2], acc[f][g][3]);
        }
    }
}

__global__ void kv_reduce_kernel() {
    int i = blockIdx.x * 256 + threadIdx.x;   // 131072 float4
    const float4* fp = (const float4*)g_fpart;
    float4 a = fp[i];
    float4 b = fp[i + 131072];
    float4 c = fp[i + 262144];
    float4 d = fp[i + 393216];
    ((float4*)g_kv)[i] = make_float4(a.x + b.x + c.x + d.x, a.y + b.y + c.y + d.y,
                                     a.z + b.z + c.z + d.z, a.w + b.w + c.w + d.w);
}

// =====================================================================
// plain tf32 GEMM (out-projection): 128x128 tiles
// =====================================================================
__global__ __launch_bounds__(256, 2)
void tf32_gemm_kernel(const float* __restrict__ A, const float* __restrict__ B,
                      float* __restrict__ C, const float* __restrict__ bias,
                      int K, int Ncols) {
    GEMM_PREAMBLE();
    const int row0 = blockIdx.x << 7;
    const int col0 = blockIdx.y << 7;

    int ar[4], akq[4], bkr[4], bnq[4];
    const float* Ap[4];
    const float* Bp[4];
#pragma unroll
    for (int l = 0; l < 4; l++) {
        int idx = tid + (l << 8);
        ar[l]  = idx >> 3;  akq[l] = idx & 7;
        Ap[l]  = A + (size_t)(row0 + ar[l]) * K + (akq[l] << 2);
        bkr[l] = idx >> 5;  bnq[l] = idx & 31;
        Bp[l]  = B + (size_t)bkr[l] * Ncols + col0 + (bnq[l] << 2);
    }

    float4 sa[4], sb[4];
    uint32_t* buf[2] = {dynsmem, dynsmem + 8192};

#pragma unroll
    for (int l = 0; l < 4; l++) {
        sa[l] = *(const float4*)(Ap[l]);
        sb[l] = *(const float4*)(Bp[l]);
    }
    sts_tile(buf[0], buf[0] + 4096, sa, sb, ar, akq, bkr, bnq);
    __syncthreads();

    int cur = 0;
    const int nIter = K >> 5;
    for (int it = 1; it < nIter; it++) {
        int k0 = it << 5;
#pragma unroll
        for (int l = 0; l < 4; l++) {
            sa[l] = *(const float4*)(Ap[l] + k0);
            sb[l] = *(const float4*)(Bp[l] + (size_t)k0 * Ncols);
        }
        mma_phase(buf[cur], buf[cur] + 4096, wm, wn, lane, acc);
        sts_tile(buf[cur ^ 1], buf[cur ^ 1] + 4096, sa, sb, ar, akq, bkr, bnq);
        __syncthreads();
        cur ^= 1;
    }
    mma_phase(buf[cur], buf[cur] + 4096, wm, wn, lane, acc);

    const int gq = lane >> 2, cq = lane & 3;
#pragma unroll
    for (int f = 0; f < 4; f++) {
        int mrow = row0 + wm + (f << 4) + gq;
#pragma unroll
        for (int g = 0; g < 4; g++) {
            int col = col0 + wn + (g << 3) + (cq << 1);
            float bx = 0.f, by = 0.f;
            if (bias) { bx = bias[col]; by = bias[col + 1]; }
            *(float2*)&C[(size_t)mrow * Ncols + col] =
                make_float2(acc[f][g][0] + bx, acc[f][g][1] + by);
            *(float2*)&C[(size_t)(mrow + 8) * Ncols + col] =
                make_float2(acc[f][g][2] + bx, acc[f][g][3] + by);
        }
    }
}

// ---------------- sum conv partials + layernorm ----------------
__device__ __forceinline__ float warpSum(float v) {
#pragma unroll
    for (int o = 16; o; o >>= 1) v += __shfl_xor_sync(0xffffffffu, v, o);
    return v;
}

__global__ void ln_kernel(const float* __restrict__ gamma, const float* __restrict__ beta) {
    const int row = blockIdx.x;
    const int tid = threadIdx.x;
    float4 v = make_float4(0.f, 0.f, 0.f, 0.f);
#pragma unroll
    for (int z = 0; z < 8; z++) {
        float4 p = *(const float4*)&g_fpart[((size_t)z * 512 + row) * 512 + (tid << 2)];
        v.x += p.x; v.y += p.y; v.z += p.z; v.w += p.w;
    }
    float s = v.x + v.y + v.z + v.w;
    float s2 = v.x * v.x + v.y * v.y + v.z * v.z + v.w * v.w;
    s = warpSum(s);
    s2 = warpSum(s2);
    __shared__ float sh[8];
    int w = tid >> 5, l = tid & 31;
    if (l == 0) { sh[w] = s; sh[4 + w] = s2; }
    __syncthreads();
    float S  = sh[0] + sh[1] + sh[2] + sh[3];
    float S2 = sh[4] + sh[5] + sh[6] + sh[7];
    float mean = S * (1.f / 512.f);
    float var = S2 * (1.f / 512.f) - mean * mean;
    float rstd = rsqrtf(var + 1e-3f);
    float4 g = *(const float4*)&gamma[tid << 2];
    float4 be = *(const float4*)&beta[tid << 2];
    float4 o;
    o.x = (v.x - mean) * rstd * g.x + be.x;
    o.y = (v.y - mean) * rstd * g.y + be.y;
    o.z = (v.z - mean) * rstd * g.z + be.z;
    o.w = (v.w - mean) * rstd * g.w + be.w;
    *(float4*)&g_ln[(size_t)row * 512 + (tid << 2)] = o;
}

// ---------------- attention (packed f32x2): per (b,nh), M=64 in shared ----------------
#define ATT_SMEM ((4096 + 4096 + 128 * 65) * 4)

union F4U {
    float4 f;
    unsigned long long u[2];
};

__global__ void attention_kernel(const float* __restrict__ q,
                                 const float* __restrict__ kv,
                                 float* __restrict__ out) {
    extern __shared__ float sm[];
    float* ks = sm;
    float* vs = sm + 4096;
    float* ps = sm + 8192;

    const int b  = blockIdx.z;
    const int nh = blockIdx.y;
    const int n0 = blockIdx.x << 7;
    const int tid = threadIdx.x;

    for (int i = tid; i < 1024; i += 128) {
        int m = i >> 4, h4 = i & 15;
        const float* base = kv + (size_t)((b << 6) + m) * 1024 + (nh << 6);
        ((float4*)ks)[i] = ((const float4*)base)[h4];
        ((float4*)vs)[i] = ((const float4*)(base + 512))[h4];
    }
    __syncthreads();

    const int row = n0 + tid;
    const float* qsrc = q + ((size_t)(b << 12) + row) * 512 + (nh << 6);
    F4U qr[16];
#pragma unroll
    for (int i = 0; i < 16; i++) qr[i].f = ((const float4*)qsrc)[i];

    float maxv = -1e30f;
    for (int m = 0; m < 64; m++) {
        const F4U* kr = (const F4U*)(ks + (m << 6));
        unsigned long long acc0 = 0ull, acc1 = 0ull;
#pragma unroll
        for (int i = 0; i < 16; i++) {
            F4U kk = kr[i];
            acc0 = ffma2(qr[i].u[0], kk.u[0], acc0);
            acc1 = ffma2(qr[i].u[1], kk.u[1], acc1);
        }
        float2 a0 = *(float2*)&acc0;
        float2 a1 = *(float2*)&acc1;
        float accv = (a0.x + a0.y) + (a1.x + a1.y);
        accv *= 0.125f;
        ps[tid * 65 + m] = accv;
        maxv = fmaxf(maxv, accv);
    }
    float ssum = 0.f;
    for (int m = 0; m < 64; m++) {
        float e = __expf(ps[tid * 65 + m] - maxv);
        ps[tid * 65 + m] = e;
        ssum += e;
    }
    const float inv = 1.f / ssum;

    F4U o[16];
#pragma unroll
    for (int i = 0; i < 16; i++) { o[i].u[0] = 0ull; o[i].u[1] = 0ull; }
    for (int m = 0; m < 64; m++) {
        unsigned long long p2 = pack2(ps[tid * 65 + m] * inv);
        const F4U* vr = (const F4U*)(vs + (m << 6));
#pragma unroll
        for (int i = 0; i < 16; i++) {
            F4U vv = vr[i];
            o[i].u[0] = ffma2(p2, vv.u[0], o[i].u[0]);
            o[i].u[1] = ffma2(p2, vv.u[1], o[i].u[1]);
        }
    }

    float4* dst = (float4*)(out + ((size_t)(b << 12) + row) * 512 + (nh << 6));
#pragma unroll
    for (int i = 0; i < 16; i++) dst[i] = o[i].f;
}

// ---------------- launch ----------------
extern "C" void kernel_launch(void* const* d_in, const int* in_sizes, int n_in,
                              void* d_out, int out_size) {
    const float* x     = (const float*)d_in[0];
    const float* Wq    = (const float*)d_in[1];
    const float* Wkv   = (const float*)d_in[2];
    const float* convw = (const float*)d_in[3];
    const float* gamma = (const float*)d_in[4];
    const float* beta  = (const float*)d_in[5];
    const float* Wp    = (const float*)d_in[6];
    const float* bp    = (const float*)d_in[7];
    float* out = (float*)d_out;

    float *p_q, *p_attn, *p_kv;
    cudaGetSymbolAddress((void**)&p_q,    g_q);
    cudaGetSymbolAddress((void**)&p_attn, g_attn);
    cudaGetSymbolAddress((void**)&p_kv,   g_kv);

    cudaFuncSetAttribute(attention_kernel,
                         cudaFuncAttributeMaxDynamicSharedMemorySize, ATT_SMEM);
    cudaFuncSetAttribute(fused_convq_kernel,
                         cudaFuncAttributeMaxDynamicSharedMemorySize, GEMM_SMEM);
    cudaFuncSetAttribute(kv_split_kernel,
                         cudaFuncAttributeMaxDynamicSharedMemorySize, GEMM_SMEM);
    cudaFuncSetAttribute(tf32_gemm_kernel,
                         cudaFuncAttributeMaxDynamicSharedMemorySize, GEMM_SMEM);

    // 1. conv patch-GEMM (128 CTAs) + q projection (1024 CTAs) fused
    fused_convq_kernel<<<1152, 256, GEMM_SMEM>>>(x, Wq, convw);
    // 2. sum conv partials + layernorm
    ln_kernel<<<512, 128>>>(gamma, beta);
    // 3. kv = ln @ Wkv, split-K=4 partials + reduce
    kv_split_kernel<<<dim3(4, 8, 4), 256, GEMM_SMEM>>>(Wkv);
    kv_reduce_kernel<<<512, 256>>>();
    // 4. attention per (b, nh)
    attention_kernel<<<dim3(32, NHH, NB), 128, ATT_SMEM>>>(p_q, p_kv, p_attn);
    // 5. final projection + bias -> d_out
    tf32_gemm_kernel<<<dim3(256, 4), 256, GEMM_SMEM>>>(p_attn, Wp, out, bp, 512, 512);
}

// round 11
// speedup vs baseline: 1.9325x; 1.9325x over previous
#include <cuda_runtime.h>
#include <math.h>
#include <stdint.h>

// Problem constants: B=8, N=4096, C=512, NH=8, HD=64, R=8, H=W=64, M=64, EPS=1e-3

#define NB   8
#define NSEQ 4096
#define CD   512
#define NHH  8

// ---------------- scratch (device globals; no allocation allowed) ----------------
__device__ uint32_t t_x[(size_t)NB * NSEQ * CD];      // tf32 x
__device__ uint32_t t_cw[(size_t)8 * 8 * 512 * 512];  // tf32 conv weights
__device__ uint32_t t_wq[512 * 512];                  // tf32 permuted Wq
__device__ uint32_t t_wkv[512 * 1024];                // tf32 Wkv
__device__ uint32_t t_wp[512 * 512];                  // tf32 Wp
__device__ uint32_t g_ln_t[512 * 512];                // tf32 layernormed fmap
__device__ uint32_t g_attn_t[(size_t)NB * NSEQ * CD]; // tf32 attention output
__device__ float    g_q[(size_t)NB * NSEQ * CD];      // fp32 queries [B,N,nh*64+hd]
__device__ float    g_fpart[(size_t)16 * 512 * 512];  // conv partials (16 z-splits)
__device__ float    g_kv[512 * 1024];                 // fp32 [B*64, 2C]

// ---------------- helpers ----------------
__device__ __forceinline__ uint32_t f2tf32(float v) {
    uint32_t u;
    asm("cvt.rna.tf32.f32 %0, %1;" : "=r"(u) : "f"(v));
    return u;
}

__device__ __forceinline__ void mma_tf32(float* d, const uint32_t* a, const uint32_t* b) {
    asm volatile(
        "mma.sync.aligned.m16n8k8.row.col.f32.tf32.tf32.f32 "
        "{%0,%1,%2,%3}, {%4,%5,%6,%7}, {%8,%9}, {%0,%1,%2,%3};"
        : "+f"(d[0]), "+f"(d[1]), "+f"(d[2]), "+f"(d[3])
        : "r"(a[0]), "r"(a[1]), "r"(a[2]), "r"(a[3]), "r"(b[0]), "r"(b[1]));
}

__device__ __forceinline__ void cp16(uint32_t dst, const void* src) {
    asm volatile("cp.async.cg.shared.global [%0], [%1], 16;" :: "r"(dst), "l"(src));
}
__device__ __forceinline__ void cp_commit() {
    asm volatile("cp.async.commit_group;");
}

__device__ __forceinline__ unsigned long long ffma2(unsigned long long a,
                                                    unsigned long long b,
                                                    unsigned long long c) {
    unsigned long long d;
    asm("fma.rn.f32x2 %0, %1, %2, %3;" : "=l"(d) : "l"(a), "l"(b), "l"(c));
    return d;
}
__device__ __forceinline__ unsigned long long pack2(float x) {
    unsigned long long r;
    asm("mov.b64 %0, {%1, %1};" : "=l"(r) : "f"(x));
    return r;
}

// ---------------- conversion kernels ----------------
__global__ void cvt4_kernel(const float4* __restrict__ s, uint4* __restrict__ d, int n4) {
    int i = blockIdx.x * 256 + threadIdx.x;
    if (i < n4) {
        float4 v = s[i];
        d[i] = make_uint4(f2tf32(v.x), f2tf32(v.y), f2tf32(v.z), f2tf32(v.w));
    }
}

// permuted Wq: dst col d = nh*64+hd <- src col hd*8+nh
__global__ void cvt_wq_kernel(const float* __restrict__ Wq) {
    int i = blockIdx.x * 256 + threadIdx.x;   // 262144
    int k = i >> 9, d = i & 511;
    t_wq[i] = f2tf32(Wq[(k << 9) + ((d & 63) << 3) + (d >> 6)]);
}

// =====================================================================
// cp.async tf32 GEMM: 128x128 CTA tile, BK=32, 8 warps of 64x32.
// Canonical padded smem (R9-validated read path, conflict-free):
//   As[128][36], Bs[32][136]; loader = 8x cp.async 16B per thread.
// 2-stage pipeline, 2 CTAs/SM.
// =====================================================================
#define SA 36
#define SB 136
#define ASTG (128 * SA)            // 4608 u32
#define STG  (ASTG + 32 * SB)      // 8960 u32
#define GEMM_SMEM (2 * STG * 4)    // 71680 B

__device__ __forceinline__ void mma_phase(const uint32_t* As, const uint32_t* Bs,
                                          int wm, int wn, int lane,
                                          float acc[4][4][4]) {
    const int g = lane >> 2, c = lane & 3;
#pragma unroll
    for (int k8 = 0; k8 < 4; k8++) {
        uint32_t a[4][4], b[4][2];
#pragma unroll
        for (int f = 0; f < 4; f++) {
            const uint32_t* base = As + (wm + (f << 4) + g) * SA + (k8 << 3) + c;
            a[f][0] = base[0];
            a[f][1] = base[8 * SA];
            a[f][2] = base[4];
            a[f][3] = base[8 * SA + 4];
        }
#pragma unroll
        for (int gi = 0; gi < 4; gi++) {
            int ni = (wn >> 3) + gi;
            const uint32_t* bb = Bs + ((k8 << 3) + c) * SB + (ni << 3) + g;
            b[gi][0] = bb[0];
            b[gi][1] = bb[4 * SB];
        }
#pragma unroll
        for (int f = 0; f < 4; f++)
#pragma unroll
            for (int gi = 0; gi < 4; gi++) mma_tf32(acc[f][gi], a[f], b[gi]);
    }
}

__global__ __launch_bounds__(256, 2)
void tf32_gemm_t(const uint32_t* __restrict__ A, const uint32_t* __restrict__ B,
                 float* __restrict__ C, const float* __restrict__ bias,
                 int K, int Ncols) {
    extern __shared__ uint32_t ds[];
    const int tid = threadIdx.x;
    const int lane = tid & 31, warp = tid >> 5;
    const int wm = (warp >> 2) << 6;
    const int wn = (warp & 3) << 5;
    const int row0 = blockIdx.x << 7;
    const int col0 = blockIdx.y << 7;

    float acc[4][4][4];
#pragma unroll
    for (int f = 0; f < 4; f++)
#pragma unroll
        for (int g = 0; g < 4; g++)
#pragma unroll
            for (int e = 0; e < 4; e++) acc[f][g][e] = 0.f;

    const uint32_t sbase = (uint32_t)__cvta_generic_to_shared(ds);
    const int acj = tid & 7, bcj = tid & 31;
    const uint32_t* Ap[4];
#pragma unroll
    for (int i = 0; i < 4; i++)
        Ap[i] = A + (size_t)(row0 + (tid >> 3) + 32 * i) * K + (acj << 2);
    const uint32_t* Bp0 = B + (size_t)(tid >> 5) * Ncols + col0 + (bcj << 2);
    const uint32_t dA0 = sbase + ((tid >> 3) * SA + (acj << 2)) * 4;
    const uint32_t dB0 = sbase + (ASTG + (tid >> 5) * SB + (bcj << 2)) * 4;

    auto issue = [&](int stage, int k0) {
        uint32_t so = stage ? (uint32_t)(STG * 4) : 0u;
#pragma unroll
        for (int i = 0; i < 4; i++) cp16(dA0 + so + i * (32 * SA * 4), Ap[i] + k0);
#pragma unroll
        for (int i = 0; i < 4; i++)
            cp16(dB0 + so + i * (8 * SB * 4), Bp0 + (size_t)k0 * Ncols + i * 8 * Ncols);
        cp_commit();
    };

    issue(0, 0);
    const int nIter = K >> 5;
    for (int it = 0; it < nIter; it++) {
        if (it + 1 < nIter) {
            issue((it + 1) & 1, (it + 1) << 5);
            asm volatile("cp.async.wait_group 1;");
        } else {
            asm volatile("cp.async.wait_group 0;");
        }
        __syncthreads();
        const uint32_t* As = ds + (it & 1) * STG;
        mma_phase(As, As + ASTG, wm, wn, lane, acc);
        __syncthreads();
    }

    const int gq = lane >> 2, cq = lane & 3;
#pragma unroll
    for (int f = 0; f < 4; f++) {
        int mrow = row0 + wm + (f << 4) + gq;
#pragma unroll
        for (int g = 0; g < 4; g++) {
            int col = col0 + wn + (g << 3) + (cq << 1);
            float bx = 0.f, by = 0.f;
            if (bias) { bx = bias[col]; by = bias[col + 1]; }
            *(float2*)&C[(size_t)mrow * Ncols + col] =
                make_float2(acc[f][g][0] + bx, acc[f][g][1] + by);
            *(float2*)&C[(size_t)(mrow + 8) * Ncols + col] =
                make_float2(acc[f][g][2] + bx, acc[f][g][3] + by);
        }
    }
}

// =====================================================================
// conv as cp.async tf32 patch-GEMM, 16-way z-split (ry x half), K=2048.
// grid = (4, 4, 16). Writes per-z partials to g_fpart.
// =====================================================================
__global__ __launch_bounds__(256, 2)
void conv_gemm_t() {
    extern __shared__ uint32_t ds[];
    const int tid = threadIdx.x;
    const int lane = tid & 31, warp = tid >> 5;
    const int wm = (warp >> 2) << 6;
    const int wn = (warp & 3) << 5;
    const int row0 = blockIdx.x << 7;
    const int col0 = blockIdx.y << 7;
    const int z = blockIdx.z;
    const int ry = z >> 1, half = z & 1;

    float acc[4][4][4];
#pragma unroll
    for (int f = 0; f < 4; f++)
#pragma unroll
        for (int g = 0; g < 4; g++)
#pragma unroll
            for (int e = 0; e < 4; e++) acc[f][g][e] = 0.f;

    const uint32_t sbase = (uint32_t)__cvta_generic_to_shared(ds);
    const int acj = tid & 7, bcj = tid & 31;
    const uint32_t* Ap[4];
#pragma unroll
    for (int i = 0; i < 4; i++) {
        int row = row0 + (tid >> 3) + 32 * i;
        int b = row >> 6, m = row & 63;
        int my = m >> 3, mx = m & 7;
        Ap[i] = t_x + ((size_t)(b << 12) + ((my << 3) + ry) * 64 + (mx << 3)) * 512
                + (half << 11) + (acj << 2);
    }
    const uint32_t* Bp0 = t_cw + (size_t)((ry << 12) + (half << 11) + (tid >> 5)) * 512
                          + col0 + (bcj << 2);
    const uint32_t dA0 = sbase + ((tid >> 3) * SA + (acj << 2)) * 4;
    const uint32_t dB0 = sbase + (ASTG + (tid >> 5) * SB + (bcj << 2)) * 4;

    auto issue = [&](int stage, int k0) {
        uint32_t so = stage ? (uint32_t)(STG * 4) : 0u;
#pragma unroll
        for (int i = 0; i < 4; i++) cp16(dA0 + so + i * (32 * SA * 4), Ap[i] + k0);
#pragma unroll
        for (int i = 0; i < 4; i++)
            cp16(dB0 + so + i * (8 * SB * 4), Bp0 + (size_t)k0 * 512 + i * 8 * 512);
        cp_commit();
    };

    issue(0, 0);
    const int nIter = 64;   // K = 2048
    for (int it = 0; it < nIter; it++) {
        if (it + 1 < nIter) {
            issue((it + 1) & 1, (it + 1) << 5);
            asm volatile("cp.async.wait_group 1;");
        } else {
            asm volatile("cp.async.wait_group 0;");
        }
        __syncthreads();
        const uint32_t* As = ds + (it & 1) * STG;
        mma_phase(As, As + ASTG, wm, wn, lane, acc);
        __syncthreads();
    }

    const int gq = lane >> 2, cq = lane & 3;
#pragma unroll
    for (int f = 0; f < 4; f++) {
        int mrow = row0 + wm + (f << 4) + gq;
#pragma unroll
        for (int g = 0; g < 4; g++) {
            int col = col0 + wn + (g << 3) + (cq << 1);
            *(float2*)&g_fpart[((size_t)z * 512 + mrow) * 512 + col] =
                make_float2(acc[f][g][0], acc[f][g][1]);
            *(float2*)&g_fpart[((size_t)z * 512 + mrow + 8) * 512 + col] =
                make_float2(acc[f][g][2], acc[f][g][3]);
        }
    }
}

// ---------------- sum conv partials + layernorm (emit tf32) ----------------
__device__ __forceinline__ float warpSum(float v) {
#pragma unroll
    for (int o = 16; o; o >>= 1) v += __shfl_xor_sync(0xffffffffu, v, o);
    return v;
}

__global__ void ln_kernel(const float* __restrict__ gamma, const float* __restrict__ beta) {
    const int row = blockIdx.x;       // 512 rows
    const int tid = threadIdx.x;      // 128 threads, 4 cols each
    float4 v = make_float4(0.f, 0.f, 0.f, 0.f);
#pragma unroll
    for (int z = 0; z < 16; z++) {
        float4 p = *(const float4*)&g_fpart[((size_t)z * 512 + row) * 512 + (tid << 2)];
        v.x += p.x; v.y += p.y; v.z += p.z; v.w += p.w;
    }
    float s = v.x + v.y + v.z + v.w;
    float s2 = v.x * v.x + v.y * v.y + v.z * v.z + v.w * v.w;
    s = warpSum(s);
    s2 = warpSum(s2);
    __shared__ float sh[8];
    int w = tid >> 5, l = tid & 31;
    if (l == 0) { sh[w] = s; sh[4 + w] = s2; }
    __syncthreads();
    float S  = sh[0] + sh[1] + sh[2] + sh[3];
    float S2 = sh[4] + sh[5] + sh[6] + sh[7];
    float mean = S * (1.f / 512.f);
    float var = S2 * (1.f / 512.f) - mean * mean;
    float rstd = rsqrtf(var + 1e-3f);
    float4 g = *(const float4*)&gamma[tid << 2];
    float4 be = *(const float4*)&beta[tid << 2];
    uint4 o;
    o.x = f2tf32((v.x - mean) * rstd * g.x + be.x);
    o.y = f2tf32((v.y - mean) * rstd * g.y + be.y);
    o.z = f2tf32((v.z - mean) * rstd * g.z + be.z);
    o.w = f2tf32((v.w - mean) * rstd * g.w + be.w);
    *(uint4*)&g_ln_t[(size_t)row * 512 + (tid << 2)] = o;
}

// ---------------- attention (packed f32x2), emits tf32 ----------------
#define ATT_SMEM ((4096 + 4096 + 128 * 65) * 4)

union F4U {
    float4 f;
    unsigned long long u[2];
};

__global__ void attention_kernel(const float* __restrict__ q,
                                 const float* __restrict__ kv) {
    extern __shared__ float sm[];
    float* ks = sm;
    float* vs = sm + 4096;
    float* ps = sm + 8192;

    const int b  = blockIdx.z;
    const int nh = blockIdx.y;
    const int n0 = blockIdx.x << 7;
    const int tid = threadIdx.x;

    for (int i = tid; i < 1024; i += 128) {
        int m = i >> 4, h4 = i & 15;
        const float* base = kv + (size_t)((b << 6) + m) * 1024 + (nh << 6);
        ((float4*)ks)[i] = ((const float4*)base)[h4];
        ((float4*)vs)[i] = ((const float4*)(base + 512))[h4];
    }
    __syncthreads();

    const int row = n0 + tid;
    const float* qsrc = q + ((size_t)(b << 12) + row) * 512 + (nh << 6);
    F4U qr[16];
#pragma unroll
    for (int i = 0; i < 16; i++) qr[i].f = ((const float4*)qsrc)[i];

    float maxv = -1e30f;
    for (int m = 0; m < 64; m++) {
        const F4U* kr = (const F4U*)(ks + (m << 6));
        unsigned long long acc0 = 0ull, acc1 = 0ull;
#pragma unroll
        for (int i = 0; i < 16; i++) {
            F4U kk = kr[i];
            acc0 = ffma2(qr[i].u[0], kk.u[0], acc0);
            acc1 = ffma2(qr[i].u[1], kk.u[1], acc1);
        }
        float2 a0 = *(float2*)&acc0;
        float2 a1 = *(float2*)&acc1;
        float accv = (a0.x + a0.y) + (a1.x + a1.y);
        accv *= 0.125f;
        ps[tid * 65 + m] = accv;
        maxv = fmaxf(maxv, accv);
    }
    float ssum = 0.f;
    for (int m = 0; m < 64; m++) {
        float e = __expf(ps[tid * 65 + m] - maxv);
        ps[tid * 65 + m] = e;
        ssum += e;
    }
    const float inv = 1.f / ssum;

    F4U o[16];
#pragma unroll
    for (int i = 0; i < 16; i++) { o[i].u[0] = 0ull; o[i].u[1] = 0ull; }
    for (int m = 0; m < 64; m++) {
        unsigned long long p2 = pack2(ps[tid * 65 + m] * inv);
        const F4U* vr = (const F4U*)(vs + (m << 6));
#pragma unroll
        for (int i = 0; i < 16; i++) {
            F4U vv = vr[i];
            o[i].u[0] = ffma2(p2, vv.u[0], o[i].u[0]);
            o[i].u[1] = ffma2(p2, vv.u[1], o[i].u[1]);
        }
    }

    uint4* dst = (uint4*)(g_attn_t + ((size_t)(b << 12) + row) * 512 + (nh << 6));
#pragma unroll
    for (int i = 0; i < 16; i++)
        dst[i] = make_uint4(f2tf32(o[i].f.x), f2tf32(o[i].f.y),
                            f2tf32(o[i].f.z), f2tf32(o[i].f.w));
}

// ---------------- launch ----------------
extern "C" void kernel_launch(void* const* d_in, const int* in_sizes, int n_in,
                              void* d_out, int out_size) {
    const float* x     = (const float*)d_in[0];
    const float* Wq    = (const float*)d_in[1];
    const float* Wkv   = (const float*)d_in[2];
    const float* convw = (const float*)d_in[3];
    const float* gamma = (const float*)d_in[4];
    const float* beta  = (const float*)d_in[5];
    const float* Wp    = (const float*)d_in[6];
    const float* bp    = (const float*)d_in[7];
    float* out = (float*)d_out;

    uint32_t *p_tx, *p_tcw, *p_twkv, *p_twp, *p_twq, *p_lnt, *p_attnt;
    float *p_q, *p_kv;
    cudaGetSymbolAddress((void**)&p_tx,    t_x);
    cudaGetSymbolAddress((void**)&p_tcw,   t_cw);
    cudaGetSymbolAddress((void**)&p_twkv,  t_wkv);
    cudaGetSymbolAddress((void**)&p_twp,   t_wp);
    cudaGetSymbolAddress((void**)&p_twq,   t_wq);
    cudaGetSymbolAddress((void**)&p_lnt,   g_ln_t);
    cudaGetSymbolAddress((void**)&p_attnt, g_attn_t);
    cudaGetSymbolAddress((void**)&p_q,     g_q);
    cudaGetSymbolAddress((void**)&p_kv,    g_kv);

    cudaFuncSetAttribute(attention_kernel,
                         cudaFuncAttributeMaxDynamicSharedMemorySize, ATT_SMEM);
    cudaFuncSetAttribute(tf32_gemm_t,
                         cudaFuncAttributeMaxDynamicSharedMemorySize, GEMM_SMEM);
    cudaFuncSetAttribute(conv_gemm_t,
                         cudaFuncAttributeMaxDynamicSharedMemorySize, GEMM_SMEM);

    // 1. pre-convert all GEMM operands to tf32 (once)
    cvt4_kernel<<<16384, 256>>>((const float4*)x,     (uint4*)p_tx,   4194304);
    cvt4_kernel<<<16384, 256>>>((const float4*)convw, (uint4*)p_tcw,  4194304);
    cvt4_kernel<<<512,   256>>>((const float4*)Wkv,   (uint4*)p_twkv, 131072);
    cvt4_kernel<<<256,   256>>>((const float4*)Wp,    (uint4*)p_twp,  65536);
    cvt_wq_kernel<<<1024, 256>>>(Wq);

    // 2. q = x @ Wq_perm   [32768 x 512]
    tf32_gemm_t<<<dim3(256, 4), 256, GEMM_SMEM>>>(p_tx, p_twq, p_q, nullptr, 512, 512);
    // 3. conv patch-GEMM, 16-way split
    conv_gemm_t<<<dim3(4, 4, 16), 256, GEMM_SMEM>>>();
    // 4. sum partials + layernorm -> tf32
    ln_kernel<<<512, 128>>>(gamma, beta);
    // 5. kv = ln @ Wkv   [512 x 1024]
    tf32_gemm_t<<<dim3(4, 8), 256, GEMM_SMEM>>>(p_lnt, p_twkv, p_kv, nullptr, 512, 1024);
    // 6. attention per (b, nh) -> tf32
    attention_kernel<<<dim3(32, NHH, NB), 128, ATT_SMEM>>>(p_q, p_kv);
    // 7. final projection + bias -> d_out
    tf32_gemm_t<<<dim3(256, 4), 256, GEMM_SMEM>>>(p_attnt, p_twp, out, bp, 512, 512);
}